// round 8
// baseline (speedup 1.0000x reference)
#include <cuda_runtime.h>
#include <cuda_fp16.h>
#include <mma.h>
#include <math.h>
#include <stdint.h>

using namespace nvcuda;

// ---------------- problem constants ----------------
#define TT 8192
#define DD 1024
#define EE 8
#define HH 3072
#define PP (TT * 2)

// ---------------- scratch (device globals; ~101 MB, R7-proven level) ----------------
__device__ int    g_counts[EE];
__device__ int    g_cursor[EE];
__device__ int    g_offsets[EE + 1];
__device__ int    g_tok[PP];
__device__ float  g_wgt[PP];
__device__ int    g_te[TT * 2];
__device__ float  g_tw[TT * 2];
__device__ __half g_h[(size_t)PP * HH];   // fp16 SwiGLU intermediate (weight folded)

__device__ __forceinline__ float silu_f(float a) { return a / (1.f + __expf(-a)); }

__device__ __forceinline__ uint4 f8h8(float4 a, float4 b) {
    __half2 h0 = __floats2half2_rn(a.x, a.y);
    __half2 h1 = __floats2half2_rn(a.z, a.w);
    __half2 h2 = __floats2half2_rn(b.x, b.y);
    __half2 h3 = __floats2half2_rn(b.z, b.w);
    uint4 u;
    u.x = *(uint32_t*)&h0; u.y = *(uint32_t*)&h1;
    u.z = *(uint32_t*)&h2; u.w = *(uint32_t*)&h3;
    return u;
}

// ---------------- init: zero output + routing counters ----------------
__global__ void k_init(float* __restrict__ out) {
    int i = blockIdx.x * blockDim.x + threadIdx.x;
    if (i < EE) { g_counts[i] = 0; g_cursor[i] = 0; }
    int stride = gridDim.x * blockDim.x;
    for (int j = i; j < TT * DD; j += stride) out[j] = 0.f;
}

// ---------------- gating ----------------
__global__ void k_gate(const float* __restrict__ x, const float* __restrict__ gw) {
    int gid = blockIdx.x * blockDim.x + threadIdx.x;
    int t = gid >> 5, lane = gid & 31;
    if (t >= TT) return;
    const float* xr = x + (size_t)t * DD;
    float acc[EE];
#pragma unroll
    for (int e = 0; e < EE; e++) acc[e] = 0.f;
    for (int d = lane; d < DD; d += 32) {
        float xv = xr[d];
        const float4* g4 = (const float4*)(gw + (size_t)d * EE);
        float4 a = g4[0], b = g4[1];
        acc[0] += xv * a.x; acc[1] += xv * a.y; acc[2] += xv * a.z; acc[3] += xv * a.w;
        acc[4] += xv * b.x; acc[5] += xv * b.y; acc[6] += xv * b.z; acc[7] += xv * b.w;
    }
#pragma unroll
    for (int e = 0; e < EE; e++)
#pragma unroll
        for (int o = 16; o; o >>= 1) acc[e] += __shfl_xor_sync(0xffffffffu, acc[e], o);
    if (lane == 0) {
        int e0 = 0;
#pragma unroll
        for (int e = 1; e < EE; e++) if (acc[e] > acc[e0]) e0 = e;
        int e1 = (e0 == 0) ? 1 : 0;
#pragma unroll
        for (int e = 0; e < EE; e++) if (e != e0 && acc[e] > acc[e1]) e1 = e;
        float w0 = 1.f / (1.f + expf(acc[e1] - acc[e0]));
        g_te[2 * t] = e0; g_te[2 * t + 1] = e1;
        g_tw[2 * t] = w0; g_tw[2 * t + 1] = 1.f - w0;
        atomicAdd(&g_counts[e0], 1);
        atomicAdd(&g_counts[e1], 1);
    }
}

__global__ void k_scan() {
    int s = 0;
    g_offsets[0] = 0;
    for (int e = 0; e < EE; e++) { s += g_counts[e]; g_offsets[e + 1] = s; }
}

__global__ void k_scatter() {
    int t = blockIdx.x * blockDim.x + threadIdx.x;
    if (t >= TT) return;
#pragma unroll
    for (int k = 0; k < 2; k++) {
        int e = g_te[2 * t + k];
        int pos = g_offsets[e] + atomicAdd(&g_cursor[e], 1);
        g_tok[pos] = t;
        g_wgt[pos] = g_tw[2 * t + k];
    }
}

// ============================================================================
// GEMM1: h = wgt * silu(x@w1) * (x@w3) — wmma, block 128M x 128N x 32K
// 8 warps = 4m x 2n; warp tile 32x64 per operand. Single smem buffer + reg prefetch.
// smem: sA 128x40h (10240B) @0, sB1 32x136h (8704B) @10240, sB3 @18944 = 27648B
// epilogue scratch (16KB) reuses [0, 16384)
// ============================================================================
__global__ void __launch_bounds__(256) k_gemm1(
    const float* __restrict__ x,
    const float* __restrict__ w1,
    const float* __restrict__ w3) {
    int e = blockIdx.z;
    int segStart = g_offsets[e];
    int segLen = g_offsets[e + 1] - segStart;
    int row0 = blockIdx.y * 128;
    if (row0 >= segLen) return;
    int n0 = blockIdx.x * 128;

    __shared__ __align__(16) char smem[27648];
    __half* sA  = (__half*)smem;             // stride 40
    __half* sB1 = (__half*)(smem + 10240);   // stride 136
    __half* sB3 = (__half*)(smem + 18944);   // stride 136
    float*  scr = (float*)smem;              // epilogue reuse

    int tid = threadIdx.x, lane = tid & 31, wid = tid >> 5;
    int warp_m = wid & 3, warp_n = wid >> 2;

    // A loader: row = tid>>1 (128 rows), 16 fp32 at (tid&1)*16
    int ar = tid >> 1, ah = (tid & 1) * 16;
    int gr_a = row0 + ar;
    bool okA = gr_a < segLen;
    const float* aptr = x + (size_t)(okA ? g_tok[segStart + gr_a] : 0) * DD + ah;
    // B loaders: krow = tid>>3 (32 rows), 16 fp32 at (tid&7)*16
    int br = tid >> 3, bc = (tid & 7) * 16;
    const float* b1ptr = w1 + ((size_t)e * DD + br) * HH + n0 + bc;
    const float* b3ptr = w3 + ((size_t)e * DD + br) * HH + n0 + bc;

    wmma::fragment<wmma::accumulator, 16, 16, 16, float> acc1[2][4], acc3[2][4];
#pragma unroll
    for (int mt = 0; mt < 2; mt++)
#pragma unroll
        for (int nt = 0; nt < 4; nt++) {
            wmma::fill_fragment(acc1[mt][nt], 0.f);
            wmma::fill_fragment(acc3[mt][nt], 0.f);
        }

    const float4 FZ = make_float4(0.f, 0.f, 0.f, 0.f);
    uint4 ra0, ra1, rb1a, rb1b, rb3a, rb3b;
    {   // prologue: stage 0 -> regs
        const float4* p = (const float4*)aptr;
        ra0 = f8h8(okA ? p[0] : FZ, okA ? p[1] : FZ);
        ra1 = f8h8(okA ? p[2] : FZ, okA ? p[3] : FZ);
        const float4* q1 = (const float4*)b1ptr;
        rb1a = f8h8(q1[0], q1[1]); rb1b = f8h8(q1[2], q1[3]);
        const float4* q3 = (const float4*)b3ptr;
        rb3a = f8h8(q3[0], q3[1]); rb3b = f8h8(q3[2], q3[3]);
    }

    const int NS = DD / 32;
    for (int s = 0; s < NS; s++) {
        *(uint4*)(sA + ar * 40 + ah)       = ra0;
        *(uint4*)(sA + ar * 40 + ah + 8)   = ra1;
        *(uint4*)(sB1 + br * 136 + bc)     = rb1a;
        *(uint4*)(sB1 + br * 136 + bc + 8) = rb1b;
        *(uint4*)(sB3 + br * 136 + bc)     = rb3a;
        *(uint4*)(sB3 + br * 136 + bc + 8) = rb3b;
        __syncthreads();
        if (s + 1 < NS) {
            const float4* p = (const float4*)(aptr + (s + 1) * 32);
            ra0 = f8h8(okA ? p[0] : FZ, okA ? p[1] : FZ);
            ra1 = f8h8(okA ? p[2] : FZ, okA ? p[3] : FZ);
            const float4* q1 = (const float4*)(b1ptr + (size_t)(s + 1) * 32 * HH);
            rb1a = f8h8(q1[0], q1[1]); rb1b = f8h8(q1[2], q1[3]);
            const float4* q3 = (const float4*)(b3ptr + (size_t)(s + 1) * 32 * HH);
            rb3a = f8h8(q3[0], q3[1]); rb3b = f8h8(q3[2], q3[3]);
        }
#pragma unroll
        for (int kt = 0; kt < 2; kt++) {
            wmma::fragment<wmma::matrix_a, 16, 16, 16, __half, wmma::row_major> af[2];
            wmma::load_matrix_sync(af[0], sA + (warp_m * 32) * 40 + kt * 16, 40);
            wmma::load_matrix_sync(af[1], sA + (warp_m * 32 + 16) * 40 + kt * 16, 40);
#pragma unroll
            for (int nt = 0; nt < 4; nt++) {
                wmma::fragment<wmma::matrix_b, 16, 16, 16, __half, wmma::row_major> bf;
                wmma::load_matrix_sync(bf, sB1 + (kt * 16) * 136 + warp_n * 64 + nt * 16, 136);
                wmma::mma_sync(acc1[0][nt], af[0], bf, acc1[0][nt]);
                wmma::mma_sync(acc1[1][nt], af[1], bf, acc1[1][nt]);
                wmma::load_matrix_sync(bf, sB3 + (kt * 16) * 136 + warp_n * 64 + nt * 16, 136);
                wmma::mma_sync(acc3[0][nt], af[0], bf, acc3[0][nt]);
                wmma::mma_sync(acc3[1][nt], af[1], bf, acc3[1][nt]);
            }
        }
        __syncthreads();
    }

    // epilogue: silu * gate * weight -> fp16 h  (scratch overlaps stage smem)
    float* w = scr + wid * 512;
    int r = lane >> 1, c = (lane & 1) * 8;
#pragma unroll
    for (int mt = 0; mt < 2; mt++) {
#pragma unroll
        for (int nt = 0; nt < 4; nt++) {
            wmma::store_matrix_sync(w, acc1[mt][nt], 16, wmma::mem_row_major);
            wmma::store_matrix_sync(w + 256, acc3[mt][nt], 16, wmma::mem_row_major);
            __syncwarp();
            int gr = row0 + warp_m * 32 + mt * 16 + r;
            if (gr < segLen) {
                float wgt = g_wgt[segStart + gr];
                __half* hp = g_h + (size_t)(segStart + gr) * HH + n0 + warp_n * 64 + nt * 16 + c;
#pragma unroll
                for (int j = 0; j < 8; j += 2) {
                    float f0 = wgt * silu_f(w[r * 16 + c + j])     * w[256 + r * 16 + c + j];
                    float f1 = wgt * silu_f(w[r * 16 + c + j + 1]) * w[256 + r * 16 + c + j + 1];
                    *(__half2*)(hp + j) = __floats2half2_rn(f0, f1);
                }
            }
            __syncwarp();
        }
    }
}

// ============================================================================
// GEMM2: out[tok] += h @ w2 — wmma, 128M x 128N x 32K
// Double-buffered smem (2 x 18944B), ONE __syncthreads per stage.
// stage layout: A @ +0 (128x40h), B @ +10240 (32x136h)
// ============================================================================
__global__ void __launch_bounds__(256) k_gemm2(
    const float* __restrict__ w2, float* __restrict__ out) {
    int e = blockIdx.z;
    int segStart = g_offsets[e];
    int segLen = g_offsets[e + 1] - segStart;
    int row0 = blockIdx.y * 128;
    if (row0 >= segLen) return;
    int n0 = blockIdx.x * 128;

    __shared__ __align__(16) char smem[2 * 18944];
    float* scr = (float*)smem;   // epilogue reuse (8KB)

    int tid = threadIdx.x, lane = tid & 31, wid = tid >> 5;
    int warp_m = wid & 3, warp_n = wid >> 2;

    int ar = tid >> 1, ah = (tid & 1) * 16;
    int gr_a = row0 + ar;
    bool okA = gr_a < segLen;
    const __half* aptr = g_h + (size_t)(segStart + (okA ? gr_a : 0)) * HH + ah;
    int br = tid >> 3, bc = (tid & 7) * 16;
    const float* bptr = w2 + ((size_t)e * HH + br) * DD + n0 + bc;

    wmma::fragment<wmma::accumulator, 16, 16, 16, float> acc[2][4];
#pragma unroll
    for (int mt = 0; mt < 2; mt++)
#pragma unroll
        for (int nt = 0; nt < 4; nt++) wmma::fill_fragment(acc[mt][nt], 0.f);

    const uint4 Z = make_uint4(0, 0, 0, 0);
    uint4 ra0, ra1, rb0, rb1;
    {   // prologue: load + store stage 0, then sync
        const uint4* p = (const uint4*)aptr;
        ra0 = okA ? p[0] : Z; ra1 = okA ? p[1] : Z;
        const float4* q = (const float4*)bptr;
        rb0 = f8h8(q[0], q[1]); rb1 = f8h8(q[2], q[3]);
        __half* dA = (__half*)smem;
        __half* dB = (__half*)(smem + 10240);
        *(uint4*)(dA + ar * 40 + ah)      = ra0;
        *(uint4*)(dA + ar * 40 + ah + 8)  = ra1;
        *(uint4*)(dB + br * 136 + bc)     = rb0;
        *(uint4*)(dB + br * 136 + bc + 8) = rb1;
    }
    __syncthreads();

    const int NS = HH / 32;
    for (int s = 0; s < NS; s++) {
        const char* buf = smem + (size_t)(s & 1) * 18944;
        if (s + 1 < NS) {   // issue next-stage global loads early
            const uint4* p = (const uint4*)(aptr + (s + 1) * 32);
            ra0 = okA ? p[0] : Z; ra1 = okA ? p[1] : Z;
            const float4* q = (const float4*)(bptr + (size_t)(s + 1) * 32 * DD);
            rb0 = f8h8(q[0], q[1]); rb1 = f8h8(q[2], q[3]);
        }
        const __half* cA = (const __half*)buf;
        const __half* cB = (const __half*)(buf + 10240);
#pragma unroll
        for (int kt = 0; kt < 2; kt++) {
            wmma::fragment<wmma::matrix_a, 16, 16, 16, __half, wmma::row_major> af[2];
            wmma::load_matrix_sync(af[0], cA + (warp_m * 32) * 40 + kt * 16, 40);
            wmma::load_matrix_sync(af[1], cA + (warp_m * 32 + 16) * 40 + kt * 16, 40);
#pragma unroll
            for (int nt = 0; nt < 4; nt++) {
                wmma::fragment<wmma::matrix_b, 16, 16, 16, __half, wmma::row_major> bf;
                wmma::load_matrix_sync(bf, cB + (kt * 16) * 136 + warp_n * 64 + nt * 16, 136);
                wmma::mma_sync(acc[0][nt], af[0], bf, acc[0][nt]);
                wmma::mma_sync(acc[1][nt], af[1], bf, acc[1][nt]);
            }
        }
        if (s + 1 < NS) {   // store next stage into the other buffer
            char* nbuf = smem + (size_t)((s + 1) & 1) * 18944;
            __half* dA = (__half*)nbuf;
            __half* dB = (__half*)(nbuf + 10240);
            *(uint4*)(dA + ar * 40 + ah)      = ra0;
            *(uint4*)(dA + ar * 40 + ah + 8)  = ra1;
            *(uint4*)(dB + br * 136 + bc)     = rb0;
            *(uint4*)(dB + br * 136 + bc + 8) = rb1;
        }
        __syncthreads();
    }

    // epilogue: atomicAdd into out (2 adds/element total across experts)
    float* w = scr + wid * 256;
    int r = lane >> 1, c = (lane & 1) * 8;
#pragma unroll
    for (int mt = 0; mt < 2; mt++) {
#pragma unroll
        for (int nt = 0; nt < 4; nt++) {
            wmma::store_matrix_sync(w, acc[mt][nt], 16, wmma::mem_row_major);
            __syncwarp();
            int gr = row0 + warp_m * 32 + mt * 16 + r;
            if (gr < segLen) {
                int tok = g_tok[segStart + gr];
                float* pp = out + (size_t)tok * DD + n0 + warp_n * 64 + nt * 16 + c;
#pragma unroll
                for (int j = 0; j < 8; j++) atomicAdd(pp + j, w[r * 16 + c + j]);
            }
            __syncwarp();
        }
    }
}

// ---------------- launch ----------------
extern "C" void kernel_launch(void* const* d_in, const int* in_sizes, int n_in,
                              void* d_out, int out_size) {
    const float* x  = (const float*)d_in[0];
    const float* gw = (const float*)d_in[1];
    const float* w1 = (const float*)d_in[2];
    const float* w3 = (const float*)d_in[3];
    const float* w2 = (const float*)d_in[4];
    float* out = (float*)d_out;

    k_init<<<4096, 256>>>(out);
    k_gate<<<TT / 8, 256>>>(x, gw);
    k_scan<<<1, 1>>>();
    k_scatter<<<TT / 256, 256>>>();
    k_gemm1<<<dim3(HH / 128, TT / 128, EE), 256>>>(x, w1, w3);
    k_gemm2<<<dim3(DD / 128, TT / 128, EE), 256>>>(w2, out);
}

// round 9
// speedup vs baseline: 1.1488x; 1.1488x over previous
#include <cuda_runtime.h>
#include <cuda_fp16.h>
#include <mma.h>
#include <math.h>
#include <stdint.h>

using namespace nvcuda;

// ---------------- problem constants ----------------
#define TT 8192
#define DD 1024
#define EE 8
#define HH 3072
#define PP (TT * 2)

// ---------------- scratch (device globals; ~101 MB, proven level) ----------------
__device__ int    g_counts[EE];
__device__ int    g_cursor[EE];
__device__ int    g_offsets[EE + 1];
__device__ int    g_tok[PP];
__device__ float  g_wgt[PP];
__device__ int    g_te[TT * 2];
__device__ float  g_tw[TT * 2];
__device__ __half g_h[(size_t)PP * HH];   // fp16 SwiGLU intermediate (weight folded)

__device__ __forceinline__ float silu_f(float a) { return a / (1.f + __expf(-a)); }

__device__ __forceinline__ uint4 f8h8(float4 a, float4 b) {
    __half2 h0 = __floats2half2_rn(a.x, a.y);
    __half2 h1 = __floats2half2_rn(a.z, a.w);
    __half2 h2 = __floats2half2_rn(b.x, b.y);
    __half2 h3 = __floats2half2_rn(b.z, b.w);
    uint4 u;
    u.x = *(uint32_t*)&h0; u.y = *(uint32_t*)&h1;
    u.z = *(uint32_t*)&h2; u.w = *(uint32_t*)&h3;
    return u;
}

// ---------------- init: zero output + routing counters ----------------
__global__ void k_init(float* __restrict__ out) {
    int i = blockIdx.x * blockDim.x + threadIdx.x;
    if (i < EE) { g_counts[i] = 0; g_cursor[i] = 0; }
    int stride = gridDim.x * blockDim.x;
    for (int j = i; j < TT * DD; j += stride) out[j] = 0.f;
}

// ---------------- gating ----------------
__global__ void k_gate(const float* __restrict__ x, const float* __restrict__ gw) {
    int gid = blockIdx.x * blockDim.x + threadIdx.x;
    int t = gid >> 5, lane = gid & 31;
    if (t >= TT) return;
    const float* xr = x + (size_t)t * DD;
    float acc[EE];
#pragma unroll
    for (int e = 0; e < EE; e++) acc[e] = 0.f;
    for (int d = lane; d < DD; d += 32) {
        float xv = xr[d];
        const float4* g4 = (const float4*)(gw + (size_t)d * EE);
        float4 a = g4[0], b = g4[1];
        acc[0] += xv * a.x; acc[1] += xv * a.y; acc[2] += xv * a.z; acc[3] += xv * a.w;
        acc[4] += xv * b.x; acc[5] += xv * b.y; acc[6] += xv * b.z; acc[7] += xv * b.w;
    }
#pragma unroll
    for (int e = 0; e < EE; e++)
#pragma unroll
        for (int o = 16; o; o >>= 1) acc[e] += __shfl_xor_sync(0xffffffffu, acc[e], o);
    if (lane == 0) {
        int e0 = 0;
#pragma unroll
        for (int e = 1; e < EE; e++) if (acc[e] > acc[e0]) e0 = e;
        int e1 = (e0 == 0) ? 1 : 0;
#pragma unroll
        for (int e = 0; e < EE; e++) if (e != e0 && acc[e] > acc[e1]) e1 = e;
        float w0 = 1.f / (1.f + expf(acc[e1] - acc[e0]));
        g_te[2 * t] = e0; g_te[2 * t + 1] = e1;
        g_tw[2 * t] = w0; g_tw[2 * t + 1] = 1.f - w0;
        atomicAdd(&g_counts[e0], 1);
        atomicAdd(&g_counts[e1], 1);
    }
}

__global__ void k_scan() {
    int s = 0;
    g_offsets[0] = 0;
    for (int e = 0; e < EE; e++) { s += g_counts[e]; g_offsets[e + 1] = s; }
}

__global__ void k_scatter() {
    int t = blockIdx.x * blockDim.x + threadIdx.x;
    if (t >= TT) return;
#pragma unroll
    for (int k = 0; k < 2; k++) {
        int e = g_te[2 * t + k];
        int pos = g_offsets[e] + atomicAdd(&g_cursor[e], 1);
        g_tok[pos] = t;
        g_wgt[pos] = g_tw[2 * t + k];
    }
}

// ============================================================================
// GEMM1: h = wgt * silu(x@w1) * (x@w3) — wmma, 128M x 64N x 32K (R7 tile)
// DOUBLE-buffered smem, ONE __syncthreads per stage.
// stage: sA 128x40h (10240B) @0, sB1 32x72h (4608B) @10240, sB3 @14848 = 19456B
// ============================================================================
__global__ void __launch_bounds__(256) k_gemm1(
    const float* __restrict__ x,
    const float* __restrict__ w1,
    const float* __restrict__ w3) {
    int e = blockIdx.z;
    int segStart = g_offsets[e];
    int segLen = g_offsets[e + 1] - segStart;
    int row0 = blockIdx.y * 128;
    if (row0 >= segLen) return;
    int n0 = blockIdx.x * 64;

    __shared__ __align__(16) char smem[2 * 19456];
    float* scr = (float*)smem;   // epilogue reuse (16KB)

    int tid = threadIdx.x, lane = tid & 31, wid = tid >> 5;
    int warp_m = wid & 3, warp_n = wid >> 2;

    // A loader: row = tid>>1, 16 fp32 at (tid&1)*16
    int ar = tid >> 1, ah = (tid & 1) * 16;
    int gr_a = row0 + ar;
    bool okA = gr_a < segLen;
    const float* aptr = x + (size_t)(okA ? g_tok[segStart + gr_a] : 0) * DD + ah;
    // B loaders: krow = tid>>3, 8 fp32 at (tid&7)*8
    int br = tid >> 3, bc = (tid & 7) * 8;
    const float* b1ptr = w1 + ((size_t)e * DD + br) * HH + n0 + bc;
    const float* b3ptr = w3 + ((size_t)e * DD + br) * HH + n0 + bc;

    wmma::fragment<wmma::accumulator, 16, 16, 16, float> acc1[2][2], acc3[2][2];
#pragma unroll
    for (int mt = 0; mt < 2; mt++)
#pragma unroll
        for (int nt = 0; nt < 2; nt++) {
            wmma::fill_fragment(acc1[mt][nt], 0.f);
            wmma::fill_fragment(acc3[mt][nt], 0.f);
        }

    const float4 FZ = make_float4(0.f, 0.f, 0.f, 0.f);
    uint4 ra0, ra1, rb1, rb3;
    {   // prologue: load + commit stage 0 to buffer 0
        const float4* p = (const float4*)aptr;
        ra0 = f8h8(okA ? p[0] : FZ, okA ? p[1] : FZ);
        ra1 = f8h8(okA ? p[2] : FZ, okA ? p[3] : FZ);
        const float4* q1 = (const float4*)b1ptr;
        rb1 = f8h8(q1[0], q1[1]);
        const float4* q3 = (const float4*)b3ptr;
        rb3 = f8h8(q3[0], q3[1]);
        __half* dA  = (__half*)smem;
        __half* dB1 = (__half*)(smem + 10240);
        __half* dB3 = (__half*)(smem + 14848);
        *(uint4*)(dA + ar * 40 + ah)     = ra0;
        *(uint4*)(dA + ar * 40 + ah + 8) = ra1;
        *(uint4*)(dB1 + br * 72 + bc)    = rb1;
        *(uint4*)(dB3 + br * 72 + bc)    = rb3;
    }
    __syncthreads();

    const int NS = DD / 32;
    for (int s = 0; s < NS; s++) {
        const char* buf = smem + (size_t)(s & 1) * 19456;
        if (s + 1 < NS) {   // issue next-stage global loads before compute
            const float4* p = (const float4*)(aptr + (s + 1) * 32);
            ra0 = f8h8(okA ? p[0] : FZ, okA ? p[1] : FZ);
            ra1 = f8h8(okA ? p[2] : FZ, okA ? p[3] : FZ);
            const float4* q1 = (const float4*)(b1ptr + (size_t)(s + 1) * 32 * HH);
            rb1 = f8h8(q1[0], q1[1]);
            const float4* q3 = (const float4*)(b3ptr + (size_t)(s + 1) * 32 * HH);
            rb3 = f8h8(q3[0], q3[1]);
        }
        const __half* cA  = (const __half*)buf;
        const __half* cB1 = (const __half*)(buf + 10240);
        const __half* cB3 = (const __half*)(buf + 14848);
#pragma unroll
        for (int kt = 0; kt < 2; kt++) {
            wmma::fragment<wmma::matrix_a, 16, 16, 16, __half, wmma::row_major> af[2];
            wmma::load_matrix_sync(af[0], cA + (warp_m * 32) * 40 + kt * 16, 40);
            wmma::load_matrix_sync(af[1], cA + (warp_m * 32 + 16) * 40 + kt * 16, 40);
#pragma unroll
            for (int nt = 0; nt < 2; nt++) {
                wmma::fragment<wmma::matrix_b, 16, 16, 16, __half, wmma::row_major> bf;
                wmma::load_matrix_sync(bf, cB1 + (kt * 16) * 72 + warp_n * 32 + nt * 16, 72);
                wmma::mma_sync(acc1[0][nt], af[0], bf, acc1[0][nt]);
                wmma::mma_sync(acc1[1][nt], af[1], bf, acc1[1][nt]);
                wmma::load_matrix_sync(bf, cB3 + (kt * 16) * 72 + warp_n * 32 + nt * 16, 72);
                wmma::mma_sync(acc3[0][nt], af[0], bf, acc3[0][nt]);
                wmma::mma_sync(acc3[1][nt], af[1], bf, acc3[1][nt]);
            }
        }
        if (s + 1 < NS) {   // commit next stage into the other buffer
            char* nbuf = smem + (size_t)((s + 1) & 1) * 19456;
            __half* dA  = (__half*)nbuf;
            __half* dB1 = (__half*)(nbuf + 10240);
            __half* dB3 = (__half*)(nbuf + 14848);
            *(uint4*)(dA + ar * 40 + ah)     = ra0;
            *(uint4*)(dA + ar * 40 + ah + 8) = ra1;
            *(uint4*)(dB1 + br * 72 + bc)    = rb1;
            *(uint4*)(dB3 + br * 72 + bc)    = rb3;
        }
        __syncthreads();
    }

    // epilogue: silu * gate * weight -> fp16 h
    float* w = scr + wid * 512;
    int r = lane >> 1, c = (lane & 1) * 8;
#pragma unroll
    for (int mt = 0; mt < 2; mt++) {
#pragma unroll
        for (int nt = 0; nt < 2; nt++) {
            wmma::store_matrix_sync(w, acc1[mt][nt], 16, wmma::mem_row_major);
            wmma::store_matrix_sync(w + 256, acc3[mt][nt], 16, wmma::mem_row_major);
            __syncwarp();
            int gr = row0 + warp_m * 32 + mt * 16 + r;
            if (gr < segLen) {
                float wgt = g_wgt[segStart + gr];
                __half* hp = g_h + (size_t)(segStart + gr) * HH + n0 + warp_n * 32 + nt * 16 + c;
#pragma unroll
                for (int j = 0; j < 8; j += 2) {
                    float f0 = wgt * silu_f(w[r * 16 + c + j])     * w[256 + r * 16 + c + j];
                    float f1 = wgt * silu_f(w[r * 16 + c + j + 1]) * w[256 + r * 16 + c + j + 1];
                    *(__half2*)(hp + j) = __floats2half2_rn(f0, f1);
                }
            }
            __syncwarp();
        }
    }
}

// ============================================================================
// GEMM2: out[tok] += h @ w2 — wmma, 128M x 128N x 32K (R8 form, kept)
// Double-buffered smem (2 x 18944B), ONE __syncthreads per stage.
// ============================================================================
__global__ void __launch_bounds__(256) k_gemm2(
    const float* __restrict__ w2, float* __restrict__ out) {
    int e = blockIdx.z;
    int segStart = g_offsets[e];
    int segLen = g_offsets[e + 1] - segStart;
    int row0 = blockIdx.y * 128;
    if (row0 >= segLen) return;
    int n0 = blockIdx.x * 128;

    __shared__ __align__(16) char smem[2 * 18944];
    float* scr = (float*)smem;

    int tid = threadIdx.x, lane = tid & 31, wid = tid >> 5;
    int warp_m = wid & 3, warp_n = wid >> 2;

    int ar = tid >> 1, ah = (tid & 1) * 16;
    int gr_a = row0 + ar;
    bool okA = gr_a < segLen;
    const __half* aptr = g_h + (size_t)(segStart + (okA ? gr_a : 0)) * HH + ah;
    int br = tid >> 3, bc = (tid & 7) * 16;
    const float* bptr = w2 + ((size_t)e * HH + br) * DD + n0 + bc;

    wmma::fragment<wmma::accumulator, 16, 16, 16, float> acc[2][4];
#pragma unroll
    for (int mt = 0; mt < 2; mt++)
#pragma unroll
        for (int nt = 0; nt < 4; nt++) wmma::fill_fragment(acc[mt][nt], 0.f);

    const uint4 Z = make_uint4(0, 0, 0, 0);
    uint4 ra0, ra1, rb0, rb1;
    {
        const uint4* p = (const uint4*)aptr;
        ra0 = okA ? p[0] : Z; ra1 = okA ? p[1] : Z;
        const float4* q = (const float4*)bptr;
        rb0 = f8h8(q[0], q[1]); rb1 = f8h8(q[2], q[3]);
        __half* dA = (__half*)smem;
        __half* dB = (__half*)(smem + 10240);
        *(uint4*)(dA + ar * 40 + ah)      = ra0;
        *(uint4*)(dA + ar * 40 + ah + 8)  = ra1;
        *(uint4*)(dB + br * 136 + bc)     = rb0;
        *(uint4*)(dB + br * 136 + bc + 8) = rb1;
    }
    __syncthreads();

    const int NS = HH / 32;
    for (int s = 0; s < NS; s++) {
        const char* buf = smem + (size_t)(s & 1) * 18944;
        if (s + 1 < NS) {
            const uint4* p = (const uint4*)(aptr + (s + 1) * 32);
            ra0 = okA ? p[0] : Z; ra1 = okA ? p[1] : Z;
            const float4* q = (const float4*)(bptr + (size_t)(s + 1) * 32 * DD);
            rb0 = f8h8(q[0], q[1]); rb1 = f8h8(q[2], q[3]);
        }
        const __half* cA = (const __half*)buf;
        const __half* cB = (const __half*)(buf + 10240);
#pragma unroll
        for (int kt = 0; kt < 2; kt++) {
            wmma::fragment<wmma::matrix_a, 16, 16, 16, __half, wmma::row_major> af[2];
            wmma::load_matrix_sync(af[0], cA + (warp_m * 32) * 40 + kt * 16, 40);
            wmma::load_matrix_sync(af[1], cA + (warp_m * 32 + 16) * 40 + kt * 16, 40);
#pragma unroll
            for (int nt = 0; nt < 4; nt++) {
                wmma::fragment<wmma::matrix_b, 16, 16, 16, __half, wmma::row_major> bf;
                wmma::load_matrix_sync(bf, cB + (kt * 16) * 136 + warp_n * 64 + nt * 16, 136);
                wmma::mma_sync(acc[0][nt], af[0], bf, acc[0][nt]);
                wmma::mma_sync(acc[1][nt], af[1], bf, acc[1][nt]);
            }
        }
        if (s + 1 < NS) {
            char* nbuf = smem + (size_t)((s + 1) & 1) * 18944;
            __half* dA = (__half*)nbuf;
            __half* dB = (__half*)(nbuf + 10240);
            *(uint4*)(dA + ar * 40 + ah)      = ra0;
            *(uint4*)(dA + ar * 40 + ah + 8)  = ra1;
            *(uint4*)(dB + br * 136 + bc)     = rb0;
            *(uint4*)(dB + br * 136 + bc + 8) = rb1;
        }
        __syncthreads();
    }

    // epilogue: atomicAdd into out
    float* w = scr + wid * 256;
    int r = lane >> 1, c = (lane & 1) * 8;
#pragma unroll
    for (int mt = 0; mt < 2; mt++) {
#pragma unroll
        for (int nt = 0; nt < 4; nt++) {
            wmma::store_matrix_sync(w, acc[mt][nt], 16, wmma::mem_row_major);
            __syncwarp();
            int gr = row0 + warp_m * 32 + mt * 16 + r;
            if (gr < segLen) {
                int tok = g_tok[segStart + gr];
                float* pp = out + (size_t)tok * DD + n0 + warp_n * 64 + nt * 16 + c;
#pragma unroll
                for (int j = 0; j < 8; j++) atomicAdd(pp + j, w[r * 16 + c + j]);
            }
            __syncwarp();
        }
    }
}

// ---------------- launch ----------------
extern "C" void kernel_launch(void* const* d_in, const int* in_sizes, int n_in,
                              void* d_out, int out_size) {
    const float* x  = (const float*)d_in[0];
    const float* gw = (const float*)d_in[1];
    const float* w1 = (const float*)d_in[2];
    const float* w3 = (const float*)d_in[3];
    const float* w2 = (const float*)d_in[4];
    float* out = (float*)d_out;

    k_init<<<4096, 256>>>(out);
    k_gate<<<TT / 8, 256>>>(x, gw);
    k_scan<<<1, 1>>>();
    k_scatter<<<TT / 256, 256>>>();
    k_gemm1<<<dim3(HH / 64, TT / 128, EE), 256>>>(x, w1, w3);
    k_gemm2<<<dim3(DD / 128, TT / 128, EE), 256>>>(w2, out);
}

// round 11
// speedup vs baseline: 1.3625x; 1.1861x over previous
#include <cuda_runtime.h>
#include <cuda_fp16.h>
#include <mma.h>
#include <math.h>
#include <stdint.h>

using namespace nvcuda;

// ---------------- problem constants ----------------
#define TT 8192
#define DD 1024
#define EE 8
#define HH 3072
#define PP (TT * 2)

// ---------------- scratch (device globals; ~167 MB) ----------------
__device__ int    g_counts[EE];
__device__ int    g_cursor[EE];
__device__ int    g_offsets[EE + 1];
__device__ int    g_tok[PP];
__device__ float  g_wgt[PP];
__device__ int    g_te[TT * 2];
__device__ float  g_tw[TT * 2];
__device__ __half g_xh[(size_t)TT * DD];       // fp16 x (16 MB)
__device__ __half g_w2h[(size_t)EE * HH * DD]; // fp16 w2 (50 MB)
__device__ __half g_h[(size_t)PP * HH];        // fp16 SwiGLU intermediate (100 MB)

__device__ __forceinline__ float silu_f(float a) { return a / (1.f + __expf(-a)); }

__device__ __forceinline__ uint4 f8h8(float4 a, float4 b) {
    __half2 h0 = __floats2half2_rn(a.x, a.y);
    __half2 h1 = __floats2half2_rn(a.z, a.w);
    __half2 h2 = __floats2half2_rn(b.x, b.y);
    __half2 h3 = __floats2half2_rn(b.z, b.w);
    uint4 u;
    u.x = *(uint32_t*)&h0; u.y = *(uint32_t*)&h1;
    u.z = *(uint32_t*)&h2; u.w = *(uint32_t*)&h3;
    return u;
}

// ---------------- init: zero output + routing counters ----------------
__global__ void k_init(float* __restrict__ out) {
    int i = blockIdx.x * blockDim.x + threadIdx.x;
    if (i < EE) { g_counts[i] = 0; g_cursor[i] = 0; }
    int stride = gridDim.x * blockDim.x;
    for (int j = i; j < TT * DD; j += stride) out[j] = 0.f;
}

// ---------------- conversions: device globals referenced DIRECTLY (the R3-R10 bug
// was passing __device__ symbols as host-side kernel args = host shadow address) ----
__global__ void k_xtoh(const float* __restrict__ in) {
    size_t i = ((size_t)blockIdx.x * blockDim.x + threadIdx.x) * 8;
    float4 a = *(const float4*)(in + i);
    float4 b = *(const float4*)(in + i + 4);
    *(uint4*)(g_xh + i) = f8h8(a, b);
}
__global__ void k_w2toh(const float* __restrict__ in) {
    size_t i = ((size_t)blockIdx.x * blockDim.x + threadIdx.x) * 8;
    float4 a = *(const float4*)(in + i);
    float4 b = *(const float4*)(in + i + 4);
    *(uint4*)(g_w2h + i) = f8h8(a, b);
}

// ---------------- gating ----------------
__global__ void k_gate(const float* __restrict__ x, const float* __restrict__ gw) {
    int gid = blockIdx.x * blockDim.x + threadIdx.x;
    int t = gid >> 5, lane = gid & 31;
    if (t >= TT) return;
    const float* xr = x + (size_t)t * DD;
    float acc[EE];
#pragma unroll
    for (int e = 0; e < EE; e++) acc[e] = 0.f;
    for (int d = lane; d < DD; d += 32) {
        float xv = xr[d];
        const float4* g4 = (const float4*)(gw + (size_t)d * EE);
        float4 a = g4[0], b = g4[1];
        acc[0] += xv * a.x; acc[1] += xv * a.y; acc[2] += xv * a.z; acc[3] += xv * a.w;
        acc[4] += xv * b.x; acc[5] += xv * b.y; acc[6] += xv * b.z; acc[7] += xv * b.w;
    }
#pragma unroll
    for (int e = 0; e < EE; e++)
#pragma unroll
        for (int o = 16; o; o >>= 1) acc[e] += __shfl_xor_sync(0xffffffffu, acc[e], o);
    if (lane == 0) {
        int e0 = 0;
#pragma unroll
        for (int e = 1; e < EE; e++) if (acc[e] > acc[e0]) e0 = e;
        int e1 = (e0 == 0) ? 1 : 0;
#pragma unroll
        for (int e = 0; e < EE; e++) if (e != e0 && acc[e] > acc[e1]) e1 = e;
        float w0 = 1.f / (1.f + expf(acc[e1] - acc[e0]));
        g_te[2 * t] = e0; g_te[2 * t + 1] = e1;
        g_tw[2 * t] = w0; g_tw[2 * t + 1] = 1.f - w0;
        atomicAdd(&g_counts[e0], 1);
        atomicAdd(&g_counts[e1], 1);
    }
}

__global__ void k_scan() {
    int s = 0;
    g_offsets[0] = 0;
    for (int e = 0; e < EE; e++) { s += g_counts[e]; g_offsets[e + 1] = s; }
}

__global__ void k_scatter() {
    int t = blockIdx.x * blockDim.x + threadIdx.x;
    if (t >= TT) return;
#pragma unroll
    for (int k = 0; k < 2; k++) {
        int e = g_te[2 * t + k];
        int pos = g_offsets[e] + atomicAdd(&g_cursor[e], 1);
        g_tok[pos] = t;
        g_wgt[pos] = g_tw[2 * t + k];
    }
}

// ============================================================================
// GEMM1: h = wgt * silu(x@w1) * (x@w3) — wmma, 128M x 64N x 32K
// Double-buffered smem, ONE __syncthreads per stage. A in fp16 (g_xh).
// stage: sA 128x40h (10240B) @0, sB1 32x72h @10240, sB3 @14848 = 19456B
// ============================================================================
__global__ void __launch_bounds__(256) k_gemm1(
    const float* __restrict__ w1,
    const float* __restrict__ w3) {
    int e = blockIdx.z;
    int segStart = g_offsets[e];
    int segLen = g_offsets[e + 1] - segStart;
    int row0 = blockIdx.y * 128;
    if (row0 >= segLen) return;
    int n0 = blockIdx.x * 64;

    __shared__ __align__(16) char smem[2 * 19456];
    float* scr = (float*)smem;   // epilogue reuse

    int tid = threadIdx.x, lane = tid & 31, wid = tid >> 5;
    int warp_m = wid & 3, warp_n = wid >> 2;

    // A loader (fp16): row = tid>>1, 16 halves at (tid&1)*16
    int ar = tid >> 1, ah = (tid & 1) * 16;
    int gr_a = row0 + ar;
    bool okA = gr_a < segLen;
    const __half* aptr = g_xh + (size_t)(okA ? g_tok[segStart + gr_a] : 0) * DD + ah;
    // B loaders (fp32 + cvt): krow = tid>>3, 8 fp32 at (tid&7)*8
    int br = tid >> 3, bc = (tid & 7) * 8;
    const float* b1ptr = w1 + ((size_t)e * DD + br) * HH + n0 + bc;
    const float* b3ptr = w3 + ((size_t)e * DD + br) * HH + n0 + bc;

    wmma::fragment<wmma::accumulator, 16, 16, 16, float> acc1[2][2], acc3[2][2];
#pragma unroll
    for (int mt = 0; mt < 2; mt++)
#pragma unroll
        for (int nt = 0; nt < 2; nt++) {
            wmma::fill_fragment(acc1[mt][nt], 0.f);
            wmma::fill_fragment(acc3[mt][nt], 0.f);
        }

    const uint4 Z = make_uint4(0, 0, 0, 0);
    uint4 ra0, ra1, rb1, rb3;
    {   // prologue: stage 0 -> buffer 0
        const uint4* p = (const uint4*)aptr;
        ra0 = okA ? p[0] : Z; ra1 = okA ? p[1] : Z;
        const float4* q1 = (const float4*)b1ptr;
        rb1 = f8h8(q1[0], q1[1]);
        const float4* q3 = (const float4*)b3ptr;
        rb3 = f8h8(q3[0], q3[1]);
        __half* dA  = (__half*)smem;
        __half* dB1 = (__half*)(smem + 10240);
        __half* dB3 = (__half*)(smem + 14848);
        *(uint4*)(dA + ar * 40 + ah)     = ra0;
        *(uint4*)(dA + ar * 40 + ah + 8) = ra1;
        *(uint4*)(dB1 + br * 72 + bc)    = rb1;
        *(uint4*)(dB3 + br * 72 + bc)    = rb3;
    }
    __syncthreads();

    const int NS = DD / 32;
    for (int s = 0; s < NS; s++) {
        const char* buf = smem + (size_t)(s & 1) * 19456;
        if (s + 1 < NS) {
            const uint4* p = (const uint4*)(aptr + (s + 1) * 32);
            ra0 = okA ? p[0] : Z; ra1 = okA ? p[1] : Z;
            const float4* q1 = (const float4*)(b1ptr + (size_t)(s + 1) * 32 * HH);
            rb1 = f8h8(q1[0], q1[1]);
            const float4* q3 = (const float4*)(b3ptr + (size_t)(s + 1) * 32 * HH);
            rb3 = f8h8(q3[0], q3[1]);
        }
        const __half* cA  = (const __half*)buf;
        const __half* cB1 = (const __half*)(buf + 10240);
        const __half* cB3 = (const __half*)(buf + 14848);
#pragma unroll
        for (int kt = 0; kt < 2; kt++) {
            wmma::fragment<wmma::matrix_a, 16, 16, 16, __half, wmma::row_major> af[2];
            wmma::load_matrix_sync(af[0], cA + (warp_m * 32) * 40 + kt * 16, 40);
            wmma::load_matrix_sync(af[1], cA + (warp_m * 32 + 16) * 40 + kt * 16, 40);
#pragma unroll
            for (int nt = 0; nt < 2; nt++) {
                wmma::fragment<wmma::matrix_b, 16, 16, 16, __half, wmma::row_major> bf;
                wmma::load_matrix_sync(bf, cB1 + (kt * 16) * 72 + warp_n * 32 + nt * 16, 72);
                wmma::mma_sync(acc1[0][nt], af[0], bf, acc1[0][nt]);
                wmma::mma_sync(acc1[1][nt], af[1], bf, acc1[1][nt]);
                wmma::load_matrix_sync(bf, cB3 + (kt * 16) * 72 + warp_n * 32 + nt * 16, 72);
                wmma::mma_sync(acc3[0][nt], af[0], bf, acc3[0][nt]);
                wmma::mma_sync(acc3[1][nt], af[1], bf, acc3[1][nt]);
            }
        }
        if (s + 1 < NS) {
            char* nbuf = smem + (size_t)((s + 1) & 1) * 19456;
            __half* dA  = (__half*)nbuf;
            __half* dB1 = (__half*)(nbuf + 10240);
            __half* dB3 = (__half*)(nbuf + 14848);
            *(uint4*)(dA + ar * 40 + ah)     = ra0;
            *(uint4*)(dA + ar * 40 + ah + 8) = ra1;
            *(uint4*)(dB1 + br * 72 + bc)    = rb1;
            *(uint4*)(dB3 + br * 72 + bc)    = rb3;
        }
        __syncthreads();
    }

    // epilogue: silu * gate * weight -> fp16 h
    float* w = scr + wid * 512;
    int r = lane >> 1, c = (lane & 1) * 8;
#pragma unroll
    for (int mt = 0; mt < 2; mt++) {
#pragma unroll
        for (int nt = 0; nt < 2; nt++) {
            wmma::store_matrix_sync(w, acc1[mt][nt], 16, wmma::mem_row_major);
            wmma::store_matrix_sync(w + 256, acc3[mt][nt], 16, wmma::mem_row_major);
            __syncwarp();
            int gr = row0 + warp_m * 32 + mt * 16 + r;
            if (gr < segLen) {
                float wgt = g_wgt[segStart + gr];
                __half* hp = g_h + (size_t)(segStart + gr) * HH + n0 + warp_n * 32 + nt * 16 + c;
#pragma unroll
                for (int j = 0; j < 8; j += 2) {
                    float f0 = wgt * silu_f(w[r * 16 + c + j])     * w[256 + r * 16 + c + j];
                    float f1 = wgt * silu_f(w[r * 16 + c + j + 1]) * w[256 + r * 16 + c + j + 1];
                    *(__half2*)(hp + j) = __floats2half2_rn(f0, f1);
                }
            }
            __syncwarp();
        }
    }
}

// ============================================================================
// GEMM2: out[tok] += h @ w2 — wmma, 128M x 128N x 32K, B in fp16 (g_w2h)
// Double-buffered smem (2 x 18944B), ONE __syncthreads per stage.
// ============================================================================
__global__ void __launch_bounds__(256) k_gemm2(float* __restrict__ out) {
    int e = blockIdx.z;
    int segStart = g_offsets[e];
    int segLen = g_offsets[e + 1] - segStart;
    int row0 = blockIdx.y * 128;
    if (row0 >= segLen) return;
    int n0 = blockIdx.x * 128;

    __shared__ __align__(16) char smem[2 * 18944];
    float* scr = (float*)smem;

    int tid = threadIdx.x, lane = tid & 31, wid = tid >> 5;
    int warp_m = wid & 3, warp_n = wid >> 2;

    int ar = tid >> 1, ah = (tid & 1) * 16;
    int gr_a = row0 + ar;
    bool okA = gr_a < segLen;
    const __half* aptr = g_h + (size_t)(segStart + (okA ? gr_a : 0)) * HH + ah;
    int br = tid >> 3, bc = (tid & 7) * 16;
    const __half* bptr = g_w2h + ((size_t)e * HH + br) * DD + n0 + bc;

    wmma::fragment<wmma::accumulator, 16, 16, 16, float> acc[2][4];
#pragma unroll
    for (int mt = 0; mt < 2; mt++)
#pragma unroll
        for (int nt = 0; nt < 4; nt++) wmma::fill_fragment(acc[mt][nt], 0.f);

    const uint4 Z = make_uint4(0, 0, 0, 0);
    uint4 ra0, ra1, rb0, rb1;
    {
        const uint4* p = (const uint4*)aptr;
        ra0 = okA ? p[0] : Z; ra1 = okA ? p[1] : Z;
        const uint4* q = (const uint4*)bptr;
        rb0 = q[0]; rb1 = q[1];
        __half* dA = (__half*)smem;
        __half* dB = (__half*)(smem + 10240);
        *(uint4*)(dA + ar * 40 + ah)      = ra0;
        *(uint4*)(dA + ar * 40 + ah + 8)  = ra1;
        *(uint4*)(dB + br * 136 + bc)     = rb0;
        *(uint4*)(dB + br * 136 + bc + 8) = rb1;
    }
    __syncthreads();

    const int NS = HH / 32;
    for (int s = 0; s < NS; s++) {
        const char* buf = smem + (size_t)(s & 1) * 18944;
        if (s + 1 < NS) {
            const uint4* p = (const uint4*)(aptr + (s + 1) * 32);
            ra0 = okA ? p[0] : Z; ra1 = okA ? p[1] : Z;
            const uint4* q = (const uint4*)(bptr + (size_t)(s + 1) * 32 * DD);
            rb0 = q[0]; rb1 = q[1];
        }
        const __half* cA = (const __half*)buf;
        const __half* cB = (const __half*)(buf + 10240);
#pragma unroll
        for (int kt = 0; kt < 2; kt++) {
            wmma::fragment<wmma::matrix_a, 16, 16, 16, __half, wmma::row_major> af[2];
            wmma::load_matrix_sync(af[0], cA + (warp_m * 32) * 40 + kt * 16, 40);
            wmma::load_matrix_sync(af[1], cA + (warp_m * 32 + 16) * 40 + kt * 16, 40);
#pragma unroll
            for (int nt = 0; nt < 4; nt++) {
                wmma::fragment<wmma::matrix_b, 16, 16, 16, __half, wmma::row_major> bf;
                wmma::load_matrix_sync(bf, cB + (kt * 16) * 136 + warp_n * 64 + nt * 16, 136);
                wmma::mma_sync(acc[0][nt], af[0], bf, acc[0][nt]);
                wmma::mma_sync(acc[1][nt], af[1], bf, acc[1][nt]);
            }
        }
        if (s + 1 < NS) {
            char* nbuf = smem + (size_t)((s + 1) & 1) * 18944;
            __half* dA = (__half*)nbuf;
            __half* dB = (__half*)(nbuf + 10240);
            *(uint4*)(dA + ar * 40 + ah)      = ra0;
            *(uint4*)(dA + ar * 40 + ah + 8)  = ra1;
            *(uint4*)(dB + br * 136 + bc)     = rb0;
            *(uint4*)(dB + br * 136 + bc + 8) = rb1;
        }
        __syncthreads();
    }

    // epilogue: atomicAdd into out
    float* w = scr + wid * 256;
    int r = lane >> 1, c = (lane & 1) * 8;
#pragma unroll
    for (int mt = 0; mt < 2; mt++) {
#pragma unroll
        for (int nt = 0; nt < 4; nt++) {
            wmma::store_matrix_sync(w, acc[mt][nt], 16, wmma::mem_row_major);
            __syncwarp();
            int gr = row0 + warp_m * 32 + mt * 16 + r;
            if (gr < segLen) {
                int tok = g_tok[segStart + gr];
                float* pp = out + (size_t)tok * DD + n0 + warp_n * 64 + nt * 16 + c;
#pragma unroll
                for (int j = 0; j < 8; j++) atomicAdd(pp + j, w[r * 16 + c + j]);
            }
            __syncwarp();
        }
    }
}

// ---------------- launch ----------------
extern "C" void kernel_launch(void* const* d_in, const int* in_sizes, int n_in,
                              void* d_out, int out_size) {
    const float* x  = (const float*)d_in[0];
    const float* gw = (const float*)d_in[1];
    const float* w1 = (const float*)d_in[2];
    const float* w3 = (const float*)d_in[3];
    const float* w2 = (const float*)d_in[4];
    float* out = (float*)d_out;

    k_init<<<4096, 256>>>(out);
    k_xtoh<<<TT * DD / 8 / 256, 256>>>(x);
    k_w2toh<<<EE * HH * DD / 8 / 256, 256>>>(w2);
    k_gate<<<TT / 8, 256>>>(x, gw);
    k_scan<<<1, 1>>>();
    k_scatter<<<TT / 256, 256>>>();
    k_gemm1<<<dim3(HH / 64, TT / 128, EE), 256>>>(w1, w3);
    k_gemm2<<<dim3(DD / 128, TT / 128, EE), 256>>>(out);
}

// round 12
// speedup vs baseline: 1.4772x; 1.0842x over previous
#include <cuda_runtime.h>
#include <cuda_fp16.h>
#include <mma.h>
#include <math.h>
#include <stdint.h>

using namespace nvcuda;

// ---------------- problem constants ----------------
#define TT 8192
#define DD 1024
#define EE 8
#define HH 3072
#define PP (TT * 2)

// ---------------- scratch (device globals; ~267 MB) ----------------
__device__ int    g_counts[EE];
__device__ int    g_cursor[EE];
__device__ int    g_offsets[EE + 1];
__device__ int    g_tok[PP];
__device__ float  g_wgt[PP];
__device__ int    g_te[TT * 2];
__device__ float  g_tw[TT * 2];
__device__ __half g_xh[(size_t)TT * DD];       // fp16 x (16 MB)
__device__ __half g_w1h[(size_t)EE * DD * HH]; // fp16 w1 (50 MB)
__device__ __half g_w3h[(size_t)EE * DD * HH]; // fp16 w3 (50 MB)
__device__ __half g_w2h[(size_t)EE * HH * DD]; // fp16 w2 (50 MB)
__device__ __half g_h[(size_t)PP * HH];        // fp16 SwiGLU intermediate (100 MB)

__device__ __forceinline__ float silu_f(float a) { return a / (1.f + __expf(-a)); }

__device__ __forceinline__ uint4 f8h8(float4 a, float4 b) {
    __half2 h0 = __floats2half2_rn(a.x, a.y);
    __half2 h1 = __floats2half2_rn(a.z, a.w);
    __half2 h2 = __floats2half2_rn(b.x, b.y);
    __half2 h3 = __floats2half2_rn(b.z, b.w);
    uint4 u;
    u.x = *(uint32_t*)&h0; u.y = *(uint32_t*)&h1;
    u.z = *(uint32_t*)&h2; u.w = *(uint32_t*)&h3;
    return u;
}

// ---------------- init: zero output + routing counters ----------------
__global__ void k_init(float* __restrict__ out) {
    int i = blockIdx.x * blockDim.x + threadIdx.x;
    if (i < EE) { g_counts[i] = 0; g_cursor[i] = 0; }
    int stride = gridDim.x * blockDim.x;
    for (int j = i; j < TT * DD; j += stride) out[j] = 0.f;
}

// ---- conversions: device globals referenced DIRECTLY (never as host-side args) ----
__global__ void k_xtoh(const float* __restrict__ in) {
    size_t i = ((size_t)blockIdx.x * blockDim.x + threadIdx.x) * 8;
    float4 a = *(const float4*)(in + i);
    float4 b = *(const float4*)(in + i + 4);
    *(uint4*)(g_xh + i) = f8h8(a, b);
}
__global__ void k_w1toh(const float* __restrict__ in) {
    size_t i = ((size_t)blockIdx.x * blockDim.x + threadIdx.x) * 8;
    float4 a = *(const float4*)(in + i);
    float4 b = *(const float4*)(in + i + 4);
    *(uint4*)(g_w1h + i) = f8h8(a, b);
}
__global__ void k_w3toh(const float* __restrict__ in) {
    size_t i = ((size_t)blockIdx.x * blockDim.x + threadIdx.x) * 8;
    float4 a = *(const float4*)(in + i);
    float4 b = *(const float4*)(in + i + 4);
    *(uint4*)(g_w3h + i) = f8h8(a, b);
}
__global__ void k_w2toh(const float* __restrict__ in) {
    size_t i = ((size_t)blockIdx.x * blockDim.x + threadIdx.x) * 8;
    float4 a = *(const float4*)(in + i);
    float4 b = *(const float4*)(in + i + 4);
    *(uint4*)(g_w2h + i) = f8h8(a, b);
}

// ---------------- gating ----------------
__global__ void k_gate(const float* __restrict__ x, const float* __restrict__ gw) {
    int gid = blockIdx.x * blockDim.x + threadIdx.x;
    int t = gid >> 5, lane = gid & 31;
    if (t >= TT) return;
    const float* xr = x + (size_t)t * DD;
    float acc[EE];
#pragma unroll
    for (int e = 0; e < EE; e++) acc[e] = 0.f;
    for (int d = lane; d < DD; d += 32) {
        float xv = xr[d];
        const float4* g4 = (const float4*)(gw + (size_t)d * EE);
        float4 a = g4[0], b = g4[1];
        acc[0] += xv * a.x; acc[1] += xv * a.y; acc[2] += xv * a.z; acc[3] += xv * a.w;
        acc[4] += xv * b.x; acc[5] += xv * b.y; acc[6] += xv * b.z; acc[7] += xv * b.w;
    }
#pragma unroll
    for (int e = 0; e < EE; e++)
#pragma unroll
        for (int o = 16; o; o >>= 1) acc[e] += __shfl_xor_sync(0xffffffffu, acc[e], o);
    if (lane == 0) {
        int e0 = 0;
#pragma unroll
        for (int e = 1; e < EE; e++) if (acc[e] > acc[e0]) e0 = e;
        int e1 = (e0 == 0) ? 1 : 0;
#pragma unroll
        for (int e = 0; e < EE; e++) if (e != e0 && acc[e] > acc[e1]) e1 = e;
        float w0 = 1.f / (1.f + expf(acc[e1] - acc[e0]));
        g_te[2 * t] = e0; g_te[2 * t + 1] = e1;
        g_tw[2 * t] = w0; g_tw[2 * t + 1] = 1.f - w0;
        atomicAdd(&g_counts[e0], 1);
        atomicAdd(&g_counts[e1], 1);
    }
}

__global__ void k_scan() {
    int s = 0;
    g_offsets[0] = 0;
    for (int e = 0; e < EE; e++) { s += g_counts[e]; g_offsets[e + 1] = s; }
}

__global__ void k_scatter() {
    int t = blockIdx.x * blockDim.x + threadIdx.x;
    if (t >= TT) return;
#pragma unroll
    for (int k = 0; k < 2; k++) {
        int e = g_te[2 * t + k];
        int pos = g_offsets[e] + atomicAdd(&g_cursor[e], 1);
        g_tok[pos] = t;
        g_wgt[pos] = g_tw[2 * t + k];
    }
}

// ============================================================================
// GEMM1: h = wgt * silu(x@w1) * (x@w3) — wmma, 128M x 64N x 32K
// Double-buffered smem, ONE __syncthreads per stage. ALL operands fp16.
// stage: sA 128x40h (10240B) @0, sB1 32x72h @10240, sB3 @14848 = 19456B
// ============================================================================
__global__ void __launch_bounds__(256) k_gemm1() {
    int e = blockIdx.z;
    int segStart = g_offsets[e];
    int segLen = g_offsets[e + 1] - segStart;
    int row0 = blockIdx.y * 128;
    if (row0 >= segLen) return;
    int n0 = blockIdx.x * 64;

    __shared__ __align__(16) char smem[2 * 19456];
    float* scr = (float*)smem;   // epilogue reuse

    int tid = threadIdx.x, lane = tid & 31, wid = tid >> 5;
    int warp_m = wid & 3, warp_n = wid >> 2;

    // A loader (fp16): row = tid>>1, 16 halves at (tid&1)*16
    int ar = tid >> 1, ah = (tid & 1) * 16;
    int gr_a = row0 + ar;
    bool okA = gr_a < segLen;
    const __half* aptr = g_xh + (size_t)(okA ? g_tok[segStart + gr_a] : 0) * DD + ah;
    // B loaders (fp16): krow = tid>>3, 8 halves at (tid&7)*8
    int br = tid >> 3, bc = (tid & 7) * 8;
    const __half* b1ptr = g_w1h + ((size_t)e * DD + br) * HH + n0 + bc;
    const __half* b3ptr = g_w3h + ((size_t)e * DD + br) * HH + n0 + bc;

    wmma::fragment<wmma::accumulator, 16, 16, 16, float> acc1[2][2], acc3[2][2];
#pragma unroll
    for (int mt = 0; mt < 2; mt++)
#pragma unroll
        for (int nt = 0; nt < 2; nt++) {
            wmma::fill_fragment(acc1[mt][nt], 0.f);
            wmma::fill_fragment(acc3[mt][nt], 0.f);
        }

    const uint4 Z = make_uint4(0, 0, 0, 0);
    uint4 ra0, ra1, rb1, rb3;
    {   // prologue: stage 0 -> buffer 0
        const uint4* p = (const uint4*)aptr;
        ra0 = okA ? p[0] : Z; ra1 = okA ? p[1] : Z;
        rb1 = *(const uint4*)b1ptr;
        rb3 = *(const uint4*)b3ptr;
        __half* dA  = (__half*)smem;
        __half* dB1 = (__half*)(smem + 10240);
        __half* dB3 = (__half*)(smem + 14848);
        *(uint4*)(dA + ar * 40 + ah)     = ra0;
        *(uint4*)(dA + ar * 40 + ah + 8) = ra1;
        *(uint4*)(dB1 + br * 72 + bc)    = rb1;
        *(uint4*)(dB3 + br * 72 + bc)    = rb3;
    }
    __syncthreads();

    const int NS = DD / 32;
    for (int s = 0; s < NS; s++) {
        const char* buf = smem + (size_t)(s & 1) * 19456;
        if (s + 1 < NS) {
            const uint4* p = (const uint4*)(aptr + (s + 1) * 32);
            ra0 = okA ? p[0] : Z; ra1 = okA ? p[1] : Z;
            rb1 = *(const uint4*)(b1ptr + (size_t)(s + 1) * 32 * HH);
            rb3 = *(const uint4*)(b3ptr + (size_t)(s + 1) * 32 * HH);
        }
        const __half* cA  = (const __half*)buf;
        const __half* cB1 = (const __half*)(buf + 10240);
        const __half* cB3 = (const __half*)(buf + 14848);
#pragma unroll
        for (int kt = 0; kt < 2; kt++) {
            wmma::fragment<wmma::matrix_a, 16, 16, 16, __half, wmma::row_major> af[2];
            wmma::load_matrix_sync(af[0], cA + (warp_m * 32) * 40 + kt * 16, 40);
            wmma::load_matrix_sync(af[1], cA + (warp_m * 32 + 16) * 40 + kt * 16, 40);
#pragma unroll
            for (int nt = 0; nt < 2; nt++) {
                wmma::fragment<wmma::matrix_b, 16, 16, 16, __half, wmma::row_major> bf;
                wmma::load_matrix_sync(bf, cB1 + (kt * 16) * 72 + warp_n * 32 + nt * 16, 72);
                wmma::mma_sync(acc1[0][nt], af[0], bf, acc1[0][nt]);
                wmma::mma_sync(acc1[1][nt], af[1], bf, acc1[1][nt]);
                wmma::load_matrix_sync(bf, cB3 + (kt * 16) * 72 + warp_n * 32 + nt * 16, 72);
                wmma::mma_sync(acc3[0][nt], af[0], bf, acc3[0][nt]);
                wmma::mma_sync(acc3[1][nt], af[1], bf, acc3[1][nt]);
            }
        }
        if (s + 1 < NS) {
            char* nbuf = smem + (size_t)((s + 1) & 1) * 19456;
            __half* dA  = (__half*)nbuf;
            __half* dB1 = (__half*)(nbuf + 10240);
            __half* dB3 = (__half*)(nbuf + 14848);
            *(uint4*)(dA + ar * 40 + ah)     = ra0;
            *(uint4*)(dA + ar * 40 + ah + 8) = ra1;
            *(uint4*)(dB1 + br * 72 + bc)    = rb1;
            *(uint4*)(dB3 + br * 72 + bc)    = rb3;
        }
        __syncthreads();
    }

    // epilogue: silu * gate * weight -> fp16 h
    float* w = scr + wid * 512;
    int r = lane >> 1, c = (lane & 1) * 8;
#pragma unroll
    for (int mt = 0; mt < 2; mt++) {
#pragma unroll
        for (int nt = 0; nt < 2; nt++) {
            wmma::store_matrix_sync(w, acc1[mt][nt], 16, wmma::mem_row_major);
            wmma::store_matrix_sync(w + 256, acc3[mt][nt], 16, wmma::mem_row_major);
            __syncwarp();
            int gr = row0 + warp_m * 32 + mt * 16 + r;
            if (gr < segLen) {
                float wgt = g_wgt[segStart + gr];
                __half* hp = g_h + (size_t)(segStart + gr) * HH + n0 + warp_n * 32 + nt * 16 + c;
#pragma unroll
                for (int j = 0; j < 8; j += 2) {
                    float f0 = wgt * silu_f(w[r * 16 + c + j])     * w[256 + r * 16 + c + j];
                    float f1 = wgt * silu_f(w[r * 16 + c + j + 1]) * w[256 + r * 16 + c + j + 1];
                    *(__half2*)(hp + j) = __floats2half2_rn(f0, f1);
                }
            }
            __syncwarp();
        }
    }
}

// ============================================================================
// GEMM2: out[tok] += h @ w2 — wmma, 128M x 128N x 32K, all fp16 operands
// Double-buffered smem (2 x 18944B), ONE __syncthreads per stage.
// ============================================================================
__global__ void __launch_bounds__(256) k_gemm2(float* __restrict__ out) {
    int e = blockIdx.z;
    int segStart = g_offsets[e];
    int segLen = g_offsets[e + 1] - segStart;
    int row0 = blockIdx.y * 128;
    if (row0 >= segLen) return;
    int n0 = blockIdx.x * 128;

    __shared__ __align__(16) char smem[2 * 18944];
    float* scr = (float*)smem;

    int tid = threadIdx.x, lane = tid & 31, wid = tid >> 5;
    int warp_m = wid & 3, warp_n = wid >> 2;

    int ar = tid >> 1, ah = (tid & 1) * 16;
    int gr_a = row0 + ar;
    bool okA = gr_a < segLen;
    const __half* aptr = g_h + (size_t)(segStart + (okA ? gr_a : 0)) * HH + ah;
    int br = tid >> 3, bc = (tid & 7) * 16;
    const __half* bptr = g_w2h + ((size_t)e * HH + br) * DD + n0 + bc;

    wmma::fragment<wmma::accumulator, 16, 16, 16, float> acc[2][4];
#pragma unroll
    for (int mt = 0; mt < 2; mt++)
#pragma unroll
        for (int nt = 0; nt < 4; nt++) wmma::fill_fragment(acc[mt][nt], 0.f);

    const uint4 Z = make_uint4(0, 0, 0, 0);
    uint4 ra0, ra1, rb0, rb1;
    {
        const uint4* p = (const uint4*)aptr;
        ra0 = okA ? p[0] : Z; ra1 = okA ? p[1] : Z;
        const uint4* q = (const uint4*)bptr;
        rb0 = q[0]; rb1 = q[1];
        __half* dA = (__half*)smem;
        __half* dB = (__half*)(smem + 10240);
        *(uint4*)(dA + ar * 40 + ah)      = ra0;
        *(uint4*)(dA + ar * 40 + ah + 8)  = ra1;
        *(uint4*)(dB + br * 136 + bc)     = rb0;
        *(uint4*)(dB + br * 136 + bc + 8) = rb1;
    }
    __syncthreads();

    const int NS = HH / 32;
    for (int s = 0; s < NS; s++) {
        const char* buf = smem + (size_t)(s & 1) * 18944;
        if (s + 1 < NS) {
            const uint4* p = (const uint4*)(aptr + (s + 1) * 32);
            ra0 = okA ? p[0] : Z; ra1 = okA ? p[1] : Z;
            const uint4* q = (const uint4*)(bptr + (size_t)(s + 1) * 32 * DD);
            rb0 = q[0]; rb1 = q[1];
        }
        const __half* cA = (const __half*)buf;
        const __half* cB = (const __half*)(buf + 10240);
#pragma unroll
        for (int kt = 0; kt < 2; kt++) {
            wmma::fragment<wmma::matrix_a, 16, 16, 16, __half, wmma::row_major> af[2];
            wmma::load_matrix_sync(af[0], cA + (warp_m * 32) * 40 + kt * 16, 40);
            wmma::load_matrix_sync(af[1], cA + (warp_m * 32 + 16) * 40 + kt * 16, 40);
#pragma unroll
            for (int nt = 0; nt < 4; nt++) {
                wmma::fragment<wmma::matrix_b, 16, 16, 16, __half, wmma::row_major> bf;
                wmma::load_matrix_sync(bf, cB + (kt * 16) * 136 + warp_n * 64 + nt * 16, 136);
                wmma::mma_sync(acc[0][nt], af[0], bf, acc[0][nt]);
                wmma::mma_sync(acc[1][nt], af[1], bf, acc[1][nt]);
            }
        }
        if (s + 1 < NS) {
            char* nbuf = smem + (size_t)((s + 1) & 1) * 18944;
            __half* dA = (__half*)nbuf;
            __half* dB = (__half*)(nbuf + 10240);
            *(uint4*)(dA + ar * 40 + ah)      = ra0;
            *(uint4*)(dA + ar * 40 + ah + 8)  = ra1;
            *(uint4*)(dB + br * 136 + bc)     = rb0;
            *(uint4*)(dB + br * 136 + bc + 8) = rb1;
        }
        __syncthreads();
    }

    // epilogue: atomicAdd into out
    float* w = scr + wid * 256;
    int r = lane >> 1, c = (lane & 1) * 8;
#pragma unroll
    for (int mt = 0; mt < 2; mt++) {
#pragma unroll
        for (int nt = 0; nt < 4; nt++) {
            wmma::store_matrix_sync(w, acc[mt][nt], 16, wmma::mem_row_major);
            __syncwarp();
            int gr = row0 + warp_m * 32 + mt * 16 + r;
            if (gr < segLen) {
                int tok = g_tok[segStart + gr];
                float* pp = out + (size_t)tok * DD + n0 + warp_n * 64 + nt * 16 + c;
#pragma unroll
                for (int j = 0; j < 8; j++) atomicAdd(pp + j, w[r * 16 + c + j]);
            }
            __syncwarp();
        }
    }
}

// ---------------- launch ----------------
extern "C" void kernel_launch(void* const* d_in, const int* in_sizes, int n_in,
                              void* d_out, int out_size) {
    const float* x  = (const float*)d_in[0];
    const float* gw = (const float*)d_in[1];
    const float* w1 = (const float*)d_in[2];
    const float* w3 = (const float*)d_in[3];
    const float* w2 = (const float*)d_in[4];
    float* out = (float*)d_out;

    k_init<<<4096, 256>>>(out);
    k_xtoh<<<TT * DD / 8 / 256, 256>>>(x);
    k_w1toh<<<EE * DD * HH / 8 / 256, 256>>>(w1);
    k_w3toh<<<EE * DD * HH / 8 / 256, 256>>>(w3);
    k_w2toh<<<EE * HH * DD / 8 / 256, 256>>>(w2);
    k_gate<<<TT / 8, 256>>>(x, gw);
    k_scan<<<1, 1>>>();
    k_scatter<<<TT / 256, 256>>>();
    k_gemm1<<<dim3(HH / 64, TT / 128, EE), 256>>>();
    k_gemm2<<<dim3(DD / 128, TT / 128, EE), 256>>>(out);
}

// round 13
// speedup vs baseline: 1.7968x; 1.2163x over previous
#include <cuda_runtime.h>
#include <cuda_fp16.h>
#include <mma.h>
#include <math.h>
#include <stdint.h>

using namespace nvcuda;

// ---------------- problem constants ----------------
#define TT 8192
#define DD 1024
#define EE 8
#define HH 3072
#define PP (TT * 2)

// ---------------- scratch (device globals; ~267 MB) ----------------
__device__ int    g_counts[EE];
__device__ int    g_cursor[EE];
__device__ int    g_offsets[EE + 1];
__device__ int    g_tok[PP];
__device__ float  g_wgt[PP];
__device__ int    g_te[TT * 2];
__device__ float  g_tw[TT * 2];
__device__ __half g_xh[(size_t)TT * DD];
__device__ __half g_w1h[(size_t)EE * DD * HH];
__device__ __half g_w3h[(size_t)EE * DD * HH];
__device__ __half g_w2h[(size_t)EE * HH * DD];
__device__ __half g_h[(size_t)PP * HH];

__device__ __forceinline__ float silu_f(float a) { return a / (1.f + __expf(-a)); }

__device__ __forceinline__ uint4 f8h8(float4 a, float4 b) {
    __half2 h0 = __floats2half2_rn(a.x, a.y);
    __half2 h1 = __floats2half2_rn(a.z, a.w);
    __half2 h2 = __floats2half2_rn(b.x, b.y);
    __half2 h3 = __floats2half2_rn(b.z, b.w);
    uint4 u;
    u.x = *(uint32_t*)&h0; u.y = *(uint32_t*)&h1;
    u.z = *(uint32_t*)&h2; u.w = *(uint32_t*)&h3;
    return u;
}
__device__ __forceinline__ uint32_t smem_u32(const void* p) {
    uint32_t a;
    asm("{ .reg .u64 t; cvta.to.shared.u64 t, %1; cvt.u32.u64 %0, t; }" : "=r"(a) : "l"(p));
    return a;
}
__device__ __forceinline__ void cp16(uint32_t dst, const void* src, uint32_t nbytes) {
    asm volatile("cp.async.cg.shared.global [%0], [%1], 16, %2;"
                 :: "r"(dst), "l"(src), "r"(nbytes));
}
__device__ __forceinline__ void cp_commit() { asm volatile("cp.async.commit_group;"); }
template <int N>
__device__ __forceinline__ void cp_wait() { asm volatile("cp.async.wait_group %0;" :: "n"(N)); }

// ---------------- init ----------------
__global__ void k_init(float* __restrict__ out) {
    int i = blockIdx.x * blockDim.x + threadIdx.x;
    if (i < EE) { g_counts[i] = 0; g_cursor[i] = 0; }
    int stride = gridDim.x * blockDim.x;
    for (int j = i; j < TT * DD; j += stride) out[j] = 0.f;
}

// ---- conversions: device globals referenced DIRECTLY (never as host-side args) ----
__global__ void k_xtoh(const float* __restrict__ in) {
    size_t i = ((size_t)blockIdx.x * blockDim.x + threadIdx.x) * 8;
    float4 a = *(const float4*)(in + i);
    float4 b = *(const float4*)(in + i + 4);
    *(uint4*)(g_xh + i) = f8h8(a, b);
}
__global__ void k_w1toh(const float* __restrict__ in) {
    size_t i = ((size_t)blockIdx.x * blockDim.x + threadIdx.x) * 8;
    float4 a = *(const float4*)(in + i);
    float4 b = *(const float4*)(in + i + 4);
    *(uint4*)(g_w1h + i) = f8h8(a, b);
}
__global__ void k_w3toh(const float* __restrict__ in) {
    size_t i = ((size_t)blockIdx.x * blockDim.x + threadIdx.x) * 8;
    float4 a = *(const float4*)(in + i);
    float4 b = *(const float4*)(in + i + 4);
    *(uint4*)(g_w3h + i) = f8h8(a, b);
}
__global__ void k_w2toh(const float* __restrict__ in) {
    size_t i = ((size_t)blockIdx.x * blockDim.x + threadIdx.x) * 8;
    float4 a = *(const float4*)(in + i);
    float4 b = *(const float4*)(in + i + 4);
    *(uint4*)(g_w2h + i) = f8h8(a, b);
}

// ---------------- gating ----------------
__global__ void k_gate(const float* __restrict__ x, const float* __restrict__ gw) {
    int gid = blockIdx.x * blockDim.x + threadIdx.x;
    int t = gid >> 5, lane = gid & 31;
    if (t >= TT) return;
    const float* xr = x + (size_t)t * DD;
    float acc[EE];
#pragma unroll
    for (int e = 0; e < EE; e++) acc[e] = 0.f;
    for (int d = lane; d < DD; d += 32) {
        float xv = xr[d];
        const float4* g4 = (const float4*)(gw + (size_t)d * EE);
        float4 a = g4[0], b = g4[1];
        acc[0] += xv * a.x; acc[1] += xv * a.y; acc[2] += xv * a.z; acc[3] += xv * a.w;
        acc[4] += xv * b.x; acc[5] += xv * b.y; acc[6] += xv * b.z; acc[7] += xv * b.w;
    }
#pragma unroll
    for (int e = 0; e < EE; e++)
#pragma unroll
        for (int o = 16; o; o >>= 1) acc[e] += __shfl_xor_sync(0xffffffffu, acc[e], o);
    if (lane == 0) {
        int e0 = 0;
#pragma unroll
        for (int e = 1; e < EE; e++) if (acc[e] > acc[e0]) e0 = e;
        int e1 = (e0 == 0) ? 1 : 0;
#pragma unroll
        for (int e = 0; e < EE; e++) if (e != e0 && acc[e] > acc[e1]) e1 = e;
        float w0 = 1.f / (1.f + expf(acc[e1] - acc[e0]));
        g_te[2 * t] = e0; g_te[2 * t + 1] = e1;
        g_tw[2 * t] = w0; g_tw[2 * t + 1] = 1.f - w0;
        atomicAdd(&g_counts[e0], 1);
        atomicAdd(&g_counts[e1], 1);
    }
}

__global__ void k_scan() {
    int s = 0;
    g_offsets[0] = 0;
    for (int e = 0; e < EE; e++) { s += g_counts[e]; g_offsets[e + 1] = s; }
}

__global__ void k_scatter() {
    int t = blockIdx.x * blockDim.x + threadIdx.x;
    if (t >= TT) return;
#pragma unroll
    for (int k = 0; k < 2; k++) {
        int e = g_te[2 * t + k];
        int pos = g_offsets[e] + atomicAdd(&g_cursor[e], 1);
        g_tok[pos] = t;
        g_wgt[pos] = g_tw[2 * t + k];
    }
}

// ============================================================================
// GEMM1: h = wgt * silu(x@w1) * (x@w3) — wmma, 128M x 64N x 32K
// 4-stage cp.async pipeline, one __syncthreads per stage.
// stage 19456B: sA(128x40h) @0, sB1(32x72h) @10240, sB3 @14848
// ============================================================================
#define STG1 19456
#define SM1_BYTES (4 * STG1)   // 77824

__global__ void __launch_bounds__(256) k_gemm1() {
    int e = blockIdx.z;
    int segStart = g_offsets[e];
    int segLen = g_offsets[e + 1] - segStart;
    int row0 = blockIdx.y * 128;
    if (row0 >= segLen) return;
    int n0 = blockIdx.x * 64;

    extern __shared__ __align__(16) char smem[];
    uint32_t sb = smem_u32(smem);
    float* scr = (float*)smem;

    int tid = threadIdx.x, lane = tid & 31, wid = tid >> 5;
    int warp_m = wid & 3, warp_n = wid >> 2;

    // A: row = tid>>1, 32B chunk at (tid&1)*32
    int ar = tid >> 1;
    uint32_t aoff = (uint32_t)ar * 80 + (uint32_t)(tid & 1) * 32;
    int gr_a = row0 + ar;
    bool okA = gr_a < segLen;
    uint32_t an = okA ? 16u : 0u;
    const __half* aptr = g_xh + (size_t)(okA ? g_tok[segStart + gr_a] : 0) * DD
                       + (tid & 1) * 16;
    // B: krow = tid>>3, 16B chunk at (tid&7)*16
    int br = tid >> 3;
    uint32_t boff = (uint32_t)br * 144 + (uint32_t)(tid & 7) * 16;
    const __half* b1ptr = g_w1h + ((size_t)e * DD + br) * HH + n0 + (tid & 7) * 8;
    const __half* b3ptr = g_w3h + ((size_t)e * DD + br) * HH + n0 + (tid & 7) * 8;

    wmma::fragment<wmma::accumulator, 16, 16, 16, float> acc1[2][2], acc3[2][2];
#pragma unroll
    for (int mt = 0; mt < 2; mt++)
#pragma unroll
        for (int nt = 0; nt < 2; nt++) {
            wmma::fill_fragment(acc1[mt][nt], 0.f);
            wmma::fill_fragment(acc3[mt][nt], 0.f);
        }

    const int NS = DD / 32;
    // prologue: issue stages 0..2
#pragma unroll
    for (int s = 0; s < 3; s++) {
        uint32_t st = sb + (uint32_t)s * STG1;
        int k0 = s * 32;
        cp16(st + aoff,              aptr + k0, an);
        cp16(st + aoff + 16,         aptr + k0 + 8, an);
        cp16(st + 10240 + boff,      b1ptr + (size_t)k0 * HH, 16u);
        cp16(st + 14848 + boff,      b3ptr + (size_t)k0 * HH, 16u);
        cp_commit();
    }

    for (int s = 0; s < NS; s++) {
        cp_wait<2>();        // stage s arrived
        __syncthreads();     // visible to all; buffer (s+3)%4 provably free
        const char* buf = smem + (size_t)(s & 3) * STG1;
        const __half* cA  = (const __half*)buf;
        const __half* cB1 = (const __half*)(buf + 10240);
        const __half* cB3 = (const __half*)(buf + 14848);
#pragma unroll
        for (int kt = 0; kt < 2; kt++) {
            wmma::fragment<wmma::matrix_a, 16, 16, 16, __half, wmma::row_major> af[2];
            wmma::load_matrix_sync(af[0], cA + (warp_m * 32) * 40 + kt * 16, 40);
            wmma::load_matrix_sync(af[1], cA + (warp_m * 32 + 16) * 40 + kt * 16, 40);
#pragma unroll
            for (int nt = 0; nt < 2; nt++) {
                wmma::fragment<wmma::matrix_b, 16, 16, 16, __half, wmma::row_major> bf;
                wmma::load_matrix_sync(bf, cB1 + (kt * 16) * 72 + warp_n * 32 + nt * 16, 72);
                wmma::mma_sync(acc1[0][nt], af[0], bf, acc1[0][nt]);
                wmma::mma_sync(acc1[1][nt], af[1], bf, acc1[1][nt]);
                wmma::load_matrix_sync(bf, cB3 + (kt * 16) * 72 + warp_n * 32 + nt * 16, 72);
                wmma::mma_sync(acc3[0][nt], af[0], bf, acc3[0][nt]);
                wmma::mma_sync(acc3[1][nt], af[1], bf, acc3[1][nt]);
            }
        }
        if (s + 3 < NS) {
            uint32_t st = sb + (uint32_t)((s + 3) & 3) * STG1;
            int k0 = (s + 3) * 32;
            cp16(st + aoff,         aptr + k0, an);
            cp16(st + aoff + 16,    aptr + k0 + 8, an);
            cp16(st + 10240 + boff, b1ptr + (size_t)k0 * HH, 16u);
            cp16(st + 14848 + boff, b3ptr + (size_t)k0 * HH, 16u);
        }
        cp_commit();   // keep group count in lockstep even on tail
    }
    cp_wait<0>();
    __syncthreads();

    // epilogue: silu * gate * weight -> fp16 h
    float* w = scr + wid * 512;
    int r = lane >> 1, c = (lane & 1) * 8;
#pragma unroll
    for (int mt = 0; mt < 2; mt++) {
#pragma unroll
        for (int nt = 0; nt < 2; nt++) {
            wmma::store_matrix_sync(w, acc1[mt][nt], 16, wmma::mem_row_major);
            wmma::store_matrix_sync(w + 256, acc3[mt][nt], 16, wmma::mem_row_major);
            __syncwarp();
            int gr = row0 + warp_m * 32 + mt * 16 + r;
            if (gr < segLen) {
                float wgt = g_wgt[segStart + gr];
                __half* hp = g_h + (size_t)(segStart + gr) * HH + n0 + warp_n * 32 + nt * 16 + c;
#pragma unroll
                for (int j = 0; j < 8; j += 2) {
                    float f0 = wgt * silu_f(w[r * 16 + c + j])     * w[256 + r * 16 + c + j];
                    float f1 = wgt * silu_f(w[r * 16 + c + j + 1]) * w[256 + r * 16 + c + j + 1];
                    *(__half2*)(hp + j) = __floats2half2_rn(f0, f1);
                }
            }
            __syncwarp();
        }
    }
}

// ============================================================================
// GEMM2: out[tok] += h @ w2 — wmma, 128M x 128N x 32K
// 4-stage cp.async pipeline, one __syncthreads per stage.
// stage 18944B: sA(128x40h) @0, sB(32x136h) @10240
// ============================================================================
#define STG2 18944
#define SM2_BYTES (4 * STG2)   // 75776

__global__ void __launch_bounds__(256) k_gemm2(float* __restrict__ out) {
    int e = blockIdx.z;
    int segStart = g_offsets[e];
    int segLen = g_offsets[e + 1] - segStart;
    int row0 = blockIdx.y * 128;
    if (row0 >= segLen) return;
    int n0 = blockIdx.x * 128;

    extern __shared__ __align__(16) char smem[];
    uint32_t sb = smem_u32(smem);
    float* scr = (float*)smem;

    int tid = threadIdx.x, lane = tid & 31, wid = tid >> 5;
    int warp_m = wid & 3, warp_n = wid >> 2;

    int ar = tid >> 1;
    uint32_t aoff = (uint32_t)ar * 80 + (uint32_t)(tid & 1) * 32;
    int gr_a = row0 + ar;
    bool okA = gr_a < segLen;
    uint32_t an = okA ? 16u : 0u;
    const __half* aptr = g_h + (size_t)(segStart + (okA ? gr_a : 0)) * HH + (tid & 1) * 16;
    int br = tid >> 3;
    uint32_t boff = (uint32_t)br * 272 + (uint32_t)(tid & 7) * 32;
    const __half* bptr = g_w2h + ((size_t)e * HH + br) * DD + n0 + (tid & 7) * 16;

    wmma::fragment<wmma::accumulator, 16, 16, 16, float> acc[2][4];
#pragma unroll
    for (int mt = 0; mt < 2; mt++)
#pragma unroll
        for (int nt = 0; nt < 4; nt++) wmma::fill_fragment(acc[mt][nt], 0.f);

    const int NS = HH / 32;
#pragma unroll
    for (int s = 0; s < 3; s++) {
        uint32_t st = sb + (uint32_t)s * STG2;
        int k0 = s * 32;
        cp16(st + aoff,          aptr + k0, an);
        cp16(st + aoff + 16,     aptr + k0 + 8, an);
        cp16(st + 10240 + boff,      bptr + (size_t)k0 * DD, 16u);
        cp16(st + 10240 + boff + 16, bptr + (size_t)k0 * DD + 8, 16u);
        cp_commit();
    }

    for (int s = 0; s < NS; s++) {
        cp_wait<2>();
        __syncthreads();
        const char* buf = smem + (size_t)(s & 3) * STG2;
        const __half* cA = (const __half*)buf;
        const __half* cB = (const __half*)(buf + 10240);
#pragma unroll
        for (int kt = 0; kt < 2; kt++) {
            wmma::fragment<wmma::matrix_a, 16, 16, 16, __half, wmma::row_major> af[2];
            wmma::load_matrix_sync(af[0], cA + (warp_m * 32) * 40 + kt * 16, 40);
            wmma::load_matrix_sync(af[1], cA + (warp_m * 32 + 16) * 40 + kt * 16, 40);
#pragma unroll
            for (int nt = 0; nt < 4; nt++) {
                wmma::fragment<wmma::matrix_b, 16, 16, 16, __half, wmma::row_major> bf;
                wmma::load_matrix_sync(bf, cB + (kt * 16) * 136 + warp_n * 64 + nt * 16, 136);
                wmma::mma_sync(acc[0][nt], af[0], bf, acc[0][nt]);
                wmma::mma_sync(acc[1][nt], af[1], bf, acc[1][nt]);
            }
        }
        if (s + 3 < NS) {
            uint32_t st = sb + (uint32_t)((s + 3) & 3) * STG2;
            int k0 = (s + 3) * 32;
            cp16(st + aoff,          aptr + k0, an);
            cp16(st + aoff + 16,     aptr + k0 + 8, an);
            cp16(st + 10240 + boff,      bptr + (size_t)k0 * DD, 16u);
            cp16(st + 10240 + boff + 16, bptr + (size_t)k0 * DD + 8, 16u);
        }
        cp_commit();
    }
    cp_wait<0>();
    __syncthreads();

    // epilogue: atomicAdd into out
    float* w = scr + wid * 256;
    int r = lane >> 1, c = (lane & 1) * 8;
#pragma unroll
    for (int mt = 0; mt < 2; mt++) {
#pragma unroll
        for (int nt = 0; nt < 4; nt++) {
            wmma::store_matrix_sync(w, acc[mt][nt], 16, wmma::mem_row_major);
            __syncwarp();
            int gr = row0 + warp_m * 32 + mt * 16 + r;
            if (gr < segLen) {
                int tok = g_tok[segStart + gr];
                float* pp = out + (size_t)tok * DD + n0 + warp_n * 64 + nt * 16 + c;
#pragma unroll
                for (int j = 0; j < 8; j++) atomicAdd(pp + j, w[r * 16 + c + j]);
            }
            __syncwarp();
        }
    }
}

// ---------------- launch ----------------
extern "C" void kernel_launch(void* const* d_in, const int* in_sizes, int n_in,
                              void* d_out, int out_size) {
    const float* x  = (const float*)d_in[0];
    const float* gw = (const float*)d_in[1];
    const float* w1 = (const float*)d_in[2];
    const float* w3 = (const float*)d_in[3];
    const float* w2 = (const float*)d_in[4];
    float* out = (float*)d_out;

    cudaFuncSetAttribute(k_gemm1, cudaFuncAttributeMaxDynamicSharedMemorySize, SM1_BYTES);
    cudaFuncSetAttribute(k_gemm2, cudaFuncAttributeMaxDynamicSharedMemorySize, SM2_BYTES);

    k_init<<<4096, 256>>>(out);
    k_xtoh<<<TT * DD / 8 / 256, 256>>>(x);
    k_w1toh<<<EE * DD * HH / 8 / 256, 256>>>(w1);
    k_w3toh<<<EE * DD * HH / 8 / 256, 256>>>(w3);
    k_w2toh<<<EE * HH * DD / 8 / 256, 256>>>(w2);
    k_gate<<<TT / 8, 256>>>(x, gw);
    k_scan<<<1, 1>>>();
    k_scatter<<<TT / 256, 256>>>();
    k_gemm1<<<dim3(HH / 64, TT / 128, EE), 256, SM1_BYTES>>>();
    k_gemm2<<<dim3(DD / 128, TT / 128, EE), 256, SM2_BYTES>>>(out);
}